// round 1
// baseline (speedup 1.0000x reference)
#include <cuda_runtime.h>
#include <cuda_bf16.h>

#define DIMC 256
#define HEADS 4
#define HEAD_DIM 64
#define KEY_DIM 32
#define HIDDEN 512
#define NB 2
#define NPIX 4096
#define EPS 1e-5f

// ---------------- scratch (static device allocations; no cudaMalloc) -------
__device__ float g_qkv[NB * HIDDEN * NPIX];   // 16 MB: qkv activations
__device__ float g_y[NB * DIMC * NPIX];       // 8 MB: attention out (+pe)
__device__ float g_wqkv[HIDDEN * DIMC];
__device__ float g_bqkv[HIDDEN];
__device__ float g_wproj[DIMC * DIMC];
__device__ float g_bproj[DIMC];
__device__ float g_wpe[DIMC * 9];
__device__ float g_bpe[DIMC];

// ---------------- fold BN into conv weights --------------------------------
__global__ void fold_kernel(
    const float* __restrict__ qkv_w, const float* __restrict__ qkv_g, const float* __restrict__ qkv_b,
    const float* __restrict__ qkv_m, const float* __restrict__ qkv_v,
    const float* __restrict__ proj_w, const float* __restrict__ proj_g, const float* __restrict__ proj_b,
    const float* __restrict__ proj_m, const float* __restrict__ proj_v,
    const float* __restrict__ pe_w, const float* __restrict__ pe_g, const float* __restrict__ pe_b,
    const float* __restrict__ pe_m, const float* __restrict__ pe_v)
{
    int stride = gridDim.x * blockDim.x;
    int t0 = blockIdx.x * blockDim.x + threadIdx.x;
    for (int i = t0; i < HIDDEN * DIMC; i += stride) {
        int o = i >> 8;
        g_wqkv[i] = qkv_w[i] * (qkv_g[o] * rsqrtf(qkv_v[o] + EPS));
    }
    for (int i = t0; i < DIMC * DIMC; i += stride) {
        int o = i >> 8;
        g_wproj[i] = proj_w[i] * (proj_g[o] * rsqrtf(proj_v[o] + EPS));
    }
    for (int i = t0; i < DIMC * 9; i += stride) {
        int c = i / 9;
        g_wpe[i] = pe_w[i] * (pe_g[c] * rsqrtf(pe_v[c] + EPS));
    }
    for (int i = t0; i < HIDDEN; i += stride) {
        float s = qkv_g[i] * rsqrtf(qkv_v[i] + EPS);
        g_bqkv[i] = qkv_b[i] - qkv_m[i] * s;
    }
    for (int i = t0; i < DIMC; i += stride) {
        float s = proj_g[i] * rsqrtf(proj_v[i] + EPS);
        g_bproj[i] = proj_b[i] - proj_m[i] * s;
        float sp = pe_g[i] * rsqrtf(pe_v[i] + EPS);
        g_bpe[i] = pe_b[i] - pe_m[i] * sp;
    }
}

// ---------------- 64x64x16 fp32 GEMM with fused bias -----------------------
// C[b, m, n] = sum_k A[m,k] * X[b,k,n] + bias[m]
__device__ __forceinline__ void gemm_body(
    const float* __restrict__ A, const float* __restrict__ X,
    const float* __restrict__ bias, float* __restrict__ C,
    int M, int K)
{
    const int N = NPIX;
    int batch = blockIdx.z;
    const float* Xb = X + (size_t)batch * K * N;
    float* Cb = C + (size_t)batch * M * N;
    int m0 = blockIdx.y * 64, n0 = blockIdx.x * 64;

    __shared__ float As[16][64];   // [k][m]
    __shared__ float Bs[16][64];   // [k][n]

    int tid = threadIdx.x;
    int tx = tid & 15, ty = tid >> 4;
    int tx4 = tx * 4, ty4 = ty * 4;
    int amm = tid >> 2;            // m row for A load
    int akq = (tid & 3) * 4;       // k quad for A load
    float acc[4][4] = {};

    for (int k0 = 0; k0 < K; k0 += 16) {
        float4 av = *(const float4*)&A[(size_t)(m0 + amm) * K + k0 + akq];
        As[akq + 0][amm] = av.x;
        As[akq + 1][amm] = av.y;
        As[akq + 2][amm] = av.z;
        As[akq + 3][amm] = av.w;
        #pragma unroll
        for (int r = 0; r < 4; r++) {
            int idx = r * 256 + tid;
            int nn = idx & 63, kk = idx >> 6;
            Bs[kk][nn] = Xb[(size_t)(k0 + kk) * N + n0 + nn];
        }
        __syncthreads();
        #pragma unroll
        for (int kk = 0; kk < 16; kk++) {
            float4 a = *(const float4*)&As[kk][ty4];
            float4 b = *(const float4*)&Bs[kk][tx4];
            float aa[4] = {a.x, a.y, a.z, a.w};
            float bb[4] = {b.x, b.y, b.z, b.w};
            #pragma unroll
            for (int i = 0; i < 4; i++)
                #pragma unroll
                for (int j = 0; j < 4; j++)
                    acc[i][j] = fmaf(aa[i], bb[j], acc[i][j]);
        }
        __syncthreads();
    }
    #pragma unroll
    for (int i = 0; i < 4; i++) {
        float bi = bias[m0 + ty4 + i];
        float4 o;
        o.x = acc[i][0] + bi; o.y = acc[i][1] + bi;
        o.z = acc[i][2] + bi; o.w = acc[i][3] + bi;
        *(float4*)&Cb[(size_t)(m0 + ty4 + i) * N + n0 + tx4] = o;
    }
}

__global__ __launch_bounds__(256) void gemm_qkv_kernel(const float* __restrict__ x) {
    gemm_body(g_wqkv, x, g_bqkv, g_qkv, HIDDEN, DIMC);
}
__global__ __launch_bounds__(256) void gemm_proj_kernel(float* __restrict__ out) {
    gemm_body(g_wproj, g_y, g_bproj, out, DIMC, DIMC);
}

// ---------------- flash attention ------------------------------------------
// Per (b, head): Q [32][4096], K [32][4096], V [64][4096] (d-major rows).
// Block: 64 queries, iterate 64-key tiles with online softmax.
__global__ __launch_bounds__(256) void attn_kernel()
{
    const float scale = 0.17677669529663687f;   // KEY_DIM^-0.5
    int ib = blockIdx.x * 64;
    int head = blockIdx.y;
    int b = blockIdx.z;
    const float* base = g_qkv + (size_t)(b * HEADS + head) * 128 * NPIX;
    const float* Qg = base;
    const float* Kg = base + 32 * NPIX;
    const float* Vg = base + 64 * NPIX;

    __shared__ float Qs[32][64];      // [d][i]
    __shared__ float U[64][68];       // K tile (rows 0..31) then V tile (rows 0..63)
    __shared__ float Ps[64][68];      // S then P = exp(S - m)
    __shared__ float row_m[64], row_l[64], corr_s[64];

    int tid = threadIdx.x;
    int tx = tid & 15, ty = tid >> 4;
    int tx4 = tx * 4, ty4 = ty * 4;

    {   // Q tile load (coalesced along i)
        int i = tid & 63, d0 = tid >> 6;
        #pragma unroll
        for (int r = 0; r < 8; r++)
            Qs[d0 + r * 4][i] = Qg[(size_t)(d0 + r * 4) * NPIX + ib + i];
    }
    if (tid < 64) { row_m[tid] = -1e30f; row_l[tid] = 0.f; }
    float acc[4][4] = {};
    __syncthreads();

    for (int jb = 0; jb < NPIX; jb += 64) {
        {   // K tile -> U[0..31][j]
            int j = tid & 63, d0 = tid >> 6;
            #pragma unroll
            for (int r = 0; r < 8; r++)
                U[d0 + r * 4][j] = Kg[(size_t)(d0 + r * 4) * NPIX + jb + j];
        }
        __syncthreads();

        // S = (Q^T K) * scale  -> Ps
        float s[4][4] = {};
        #pragma unroll
        for (int d = 0; d < 32; d++) {
            float4 q = *(const float4*)&Qs[d][ty4];
            float4 k = *(const float4*)&U[d][tx4];
            float qa[4] = {q.x, q.y, q.z, q.w};
            float ka[4] = {k.x, k.y, k.z, k.w};
            #pragma unroll
            for (int i = 0; i < 4; i++)
                #pragma unroll
                for (int j = 0; j < 4; j++)
                    s[i][j] = fmaf(qa[i], ka[j], s[i][j]);
        }
        #pragma unroll
        for (int i = 0; i < 4; i++) {
            float4 o;
            o.x = s[i][0] * scale; o.y = s[i][1] * scale;
            o.z = s[i][2] * scale; o.w = s[i][3] * scale;
            *(float4*)&Ps[ty4 + i][tx4] = o;
        }
        __syncthreads();   // K reads done; Ps complete

        // online softmax: 4 threads per row (lanes 4r..4r+3 of each warp)
        {
            int r = tid >> 2, p = tid & 3;
            float* row = &Ps[r][p * 16];
            float mx = -1e30f;
            #pragma unroll
            for (int q = 0; q < 16; q++) mx = fmaxf(mx, row[q]);
            mx = fmaxf(mx, __shfl_xor_sync(0xffffffffu, mx, 1));
            mx = fmaxf(mx, __shfl_xor_sync(0xffffffffu, mx, 2));
            float m_old = row_m[r];
            float m_new = fmaxf(m_old, mx);
            float lsum = 0.f;
            #pragma unroll
            for (int q = 0; q < 16; q++) {
                float e = __expf(row[q] - m_new);
                row[q] = e;
                lsum += e;
            }
            lsum += __shfl_xor_sync(0xffffffffu, lsum, 1);
            lsum += __shfl_xor_sync(0xffffffffu, lsum, 2);
            if (p == 0) {
                float c = __expf(m_old - m_new);
                corr_s[r] = c;
                row_m[r] = m_new;
                row_l[r] = row_l[r] * c + lsum;
            }
        }
        {   // V tile -> U[0..63][j] (K is dead after the sync above)
            int j = tid & 63, d0 = tid >> 6;
            #pragma unroll
            for (int r = 0; r < 16; r++)
                U[d0 + r * 4][j] = Vg[(size_t)(d0 + r * 4) * NPIX + jb + j];
        }
        __syncthreads();

        // rescale accumulators, then O += P V^T
        float cc[4];
        #pragma unroll
        for (int i = 0; i < 4; i++) cc[i] = corr_s[ty4 + i];
        #pragma unroll
        for (int i = 0; i < 4; i++)
            #pragma unroll
            for (int j = 0; j < 4; j++)
                acc[i][j] *= cc[i];

        for (int j = 0; j < 64; j += 4) {
            float4 p[4], v[4];
            #pragma unroll
            for (int ii = 0; ii < 4; ii++) p[ii] = *(const float4*)&Ps[ty4 + ii][j];
            #pragma unroll
            for (int dd = 0; dd < 4; dd++) v[dd] = *(const float4*)&U[tx4 + dd][j];
            #pragma unroll
            for (int ii = 0; ii < 4; ii++)
                #pragma unroll
                for (int dd = 0; dd < 4; dd++) {
                    acc[ii][dd] = fmaf(p[ii].x, v[dd].x, acc[ii][dd]);
                    acc[ii][dd] = fmaf(p[ii].y, v[dd].y, acc[ii][dd]);
                    acc[ii][dd] = fmaf(p[ii].z, v[dd].z, acc[ii][dd]);
                    acc[ii][dd] = fmaf(p[ii].w, v[dd].w, acc[ii][dd]);
                }
        }
        __syncthreads();   // before next K tile overwrites U / Ps
    }

    // epilogue: normalize, stage through smem for coalesced store
    float invl[4];
    #pragma unroll
    for (int i = 0; i < 4; i++) invl[i] = 1.f / row_l[ty4 + i];
    #pragma unroll
    for (int ii = 0; ii < 4; ii++)
        #pragma unroll
        for (int dd = 0; dd < 4; dd++)
            U[tx4 + dd][ty4 + ii] = acc[ii][dd] * invl[ii];
    __syncthreads();
    {
        float* yout = g_y + ((size_t)b * DIMC + head * 64) * NPIX + ib;
        int i = tid & 63, d0 = tid >> 6;
        #pragma unroll
        for (int r = 0; r < 16; r++)
            yout[(size_t)(d0 + r * 4) * NPIX + i] = U[d0 + r * 4][i];
    }
}

// ---------------- depthwise 3x3 pe conv + residual add ---------------------
__global__ __launch_bounds__(256) void pe_add_kernel()
{
    int idx = blockIdx.x * 256 + threadIdx.x;
    if (idx >= NB * DIMC * NPIX) return;
    int n = idx & 4095;
    int c = (idx >> 12) & 255;
    int b = idx >> 20;
    int hh = n >> 6, ww = n & 63;
    int head = c >> 6, dv = c & 63;
    const float* V = g_qkv + ((size_t)(b * HEADS + head) * 128 + 64 + dv) * NPIX;
    const float* w = g_wpe + c * 9;
    float s = g_bpe[c];
    #pragma unroll
    for (int ky = -1; ky <= 1; ky++) {
        int yy = hh + ky;
        if (yy < 0 || yy > 63) continue;
        #pragma unroll
        for (int kx = -1; kx <= 1; kx++) {
            int xx = ww + kx;
            if (xx < 0 || xx > 63) continue;
            s = fmaf(w[(ky + 1) * 3 + kx + 1], V[yy * 64 + xx], s);
        }
    }
    g_y[idx] += s;
}

// ---------------- launch ----------------------------------------------------
extern "C" void kernel_launch(void* const* d_in, const int* in_sizes, int n_in,
                              void* d_out, int out_size)
{
    const float* x = (const float*)d_in[0];
    fold_kernel<<<64, 256>>>(
        (const float*)d_in[1], (const float*)d_in[2], (const float*)d_in[3],
        (const float*)d_in[4], (const float*)d_in[5],
        (const float*)d_in[6], (const float*)d_in[7], (const float*)d_in[8],
        (const float*)d_in[9], (const float*)d_in[10],
        (const float*)d_in[11], (const float*)d_in[12], (const float*)d_in[13],
        (const float*)d_in[14], (const float*)d_in[15]);

    dim3 gq(NPIX / 64, HIDDEN / 64, NB);
    gemm_qkv_kernel<<<gq, 256>>>(x);

    dim3 ga(NPIX / 64, HEADS, NB);
    attn_kernel<<<ga, 256>>>();

    pe_add_kernel<<<(NB * DIMC * NPIX) / 256, 256>>>();

    dim3 gp(NPIX / 64, DIMC / 64, NB);
    gemm_proj_kernel<<<gp, 256>>>((float*)d_out);
}

// round 3
// speedup vs baseline: 2.0360x; 2.0360x over previous
#include <cuda_runtime.h>
#include <cuda_bf16.h>

#define DIMC 256
#define HEADS 4
#define HEAD_DIM 64
#define KEY_DIM 32
#define HIDDEN 512
#define NB 2
#define NPIX 4096
#define EPS 1e-5f

typedef unsigned long long u64;

// ---------------- packed f32x2 helpers --------------------------------------
__device__ __forceinline__ u64 pk2(float lo, float hi) {
    u64 r; asm("mov.b64 %0, {%1, %2};" : "=l"(r) : "f"(lo), "f"(hi)); return r;
}
__device__ __forceinline__ u64 bc2(float v) { return pk2(v, v); }
__device__ __forceinline__ void fma2(u64& d, u64 a, u64 b) {
    asm("fma.rn.f32x2 %0, %1, %2, %0;" : "+l"(d) : "l"(a), "l"(b));
}
__device__ __forceinline__ void mul2(u64& d, u64 a) {
    asm("mul.rn.f32x2 %0, %0, %1;" : "+l"(d) : "l"(a));
}
__device__ __forceinline__ u64 add2(u64 a, u64 b) {
    u64 r; asm("add.rn.f32x2 %0, %1, %2;" : "=l"(r) : "l"(a), "l"(b)); return r;
}
__device__ __forceinline__ void up2(u64 v, float& lo, float& hi) {
    asm("mov.b64 {%0, %1}, %2;" : "=f"(lo), "=f"(hi) : "l"(v));
}

// ---------------- scratch ---------------------------------------------------
__device__ float g_qkv[NB * HIDDEN * NPIX];
__device__ float g_y[NB * DIMC * NPIX];
__device__ float g_wqkv[HIDDEN * DIMC];
__device__ float g_bqkv[HIDDEN];
__device__ float g_wproj[DIMC * DIMC];
__device__ float g_bproj[DIMC];
__device__ float g_wpe[DIMC * 9];
__device__ float g_bpe[DIMC];

// ---------------- fold BN into conv weights --------------------------------
__global__ void fold_kernel(
    const float* __restrict__ qkv_w, const float* __restrict__ qkv_g, const float* __restrict__ qkv_b,
    const float* __restrict__ qkv_m, const float* __restrict__ qkv_v,
    const float* __restrict__ proj_w, const float* __restrict__ proj_g, const float* __restrict__ proj_b,
    const float* __restrict__ proj_m, const float* __restrict__ proj_v,
    const float* __restrict__ pe_w, const float* __restrict__ pe_g, const float* __restrict__ pe_b,
    const float* __restrict__ pe_m, const float* __restrict__ pe_v)
{
    int stride = gridDim.x * blockDim.x;
    int t0 = blockIdx.x * blockDim.x + threadIdx.x;
    for (int i = t0; i < HIDDEN * DIMC; i += stride) {
        int o = i >> 8;
        g_wqkv[i] = qkv_w[i] * (qkv_g[o] * rsqrtf(qkv_v[o] + EPS));
    }
    for (int i = t0; i < DIMC * DIMC; i += stride) {
        int o = i >> 8;
        g_wproj[i] = proj_w[i] * (proj_g[o] * rsqrtf(proj_v[o] + EPS));
    }
    for (int i = t0; i < DIMC * 9; i += stride) {
        int c = i / 9;
        g_wpe[i] = pe_w[i] * (pe_g[c] * rsqrtf(pe_v[c] + EPS));
    }
    for (int i = t0; i < HIDDEN; i += stride) {
        float s = qkv_g[i] * rsqrtf(qkv_v[i] + EPS);
        g_bqkv[i] = qkv_b[i] - qkv_m[i] * s;
    }
    for (int i = t0; i < DIMC; i += stride) {
        float s = proj_g[i] * rsqrtf(proj_v[i] + EPS);
        g_bproj[i] = proj_b[i] - proj_m[i] * s;
        float sp = pe_g[i] * rsqrtf(pe_v[i] + EPS);
        g_bpe[i] = pe_b[i] - pe_m[i] * sp;
    }
}

// ---------------- 128x128 f32x2 GEMM with fused bias ------------------------
// C[b,m,n] = sum_k A[m,k] * X[b,k,n] + bias[m]
__device__ __forceinline__ void gemm128_body(
    const float* __restrict__ A, const float* __restrict__ X,
    const float* __restrict__ bias, float* __restrict__ C, int K)
{
    const int N = NPIX;
    int batch = blockIdx.z;
    const float* Xb = X + (size_t)batch * K * N;
    float* Cb = C + (size_t)batch * ((size_t)gridDim.y * 128) * N;
    int m0 = blockIdx.y * 128, n0 = blockIdx.x * 128;

    __shared__ float As[16][132];
    __shared__ float Bs[16][128];

    int tid = threadIdx.x;
    int tx = tid & 15, ty = tid >> 4;
    int tx4 = tx * 4, ty4 = ty * 4;

    u64 acc[8][4];
    #pragma unroll
    for (int i = 0; i < 8; i++)
        #pragma unroll
        for (int j = 0; j < 4; j++) acc[i][j] = 0ull;

    int mrow = tid >> 1, kq = (tid & 1) * 8;

    for (int k0 = 0; k0 < K; k0 += 16) {
        float4 a0 = *(const float4*)&A[(size_t)(m0 + mrow) * K + k0 + kq];
        float4 a1 = *(const float4*)&A[(size_t)(m0 + mrow) * K + k0 + kq + 4];
        As[kq + 0][mrow] = a0.x; As[kq + 1][mrow] = a0.y;
        As[kq + 2][mrow] = a0.z; As[kq + 3][mrow] = a0.w;
        As[kq + 4][mrow] = a1.x; As[kq + 5][mrow] = a1.y;
        As[kq + 6][mrow] = a1.z; As[kq + 7][mrow] = a1.w;
        #pragma unroll
        for (int r = 0; r < 8; r++) {
            int idx = r * 256 + tid;
            int nn = idx & 127, kk = idx >> 7;
            Bs[kk][nn] = Xb[(size_t)(k0 + kk) * N + n0 + nn];
        }
        __syncthreads();
        #pragma unroll
        for (int kk = 0; kk < 16; kk++) {
            float4 qa = *(const float4*)&As[kk][ty4];
            float4 qb = *(const float4*)&As[kk][64 + ty4];
            u64 b0 = *(const u64*)&Bs[kk][tx4];
            u64 b1 = *(const u64*)&Bs[kk][tx4 + 2];
            u64 b2 = *(const u64*)&Bs[kk][64 + tx4];
            u64 b3 = *(const u64*)&Bs[kk][64 + tx4 + 2];
            u64 am[8] = {bc2(qa.x), bc2(qa.y), bc2(qa.z), bc2(qa.w),
                         bc2(qb.x), bc2(qb.y), bc2(qb.z), bc2(qb.w)};
            #pragma unroll
            for (int mi = 0; mi < 8; mi++) {
                fma2(acc[mi][0], am[mi], b0);
                fma2(acc[mi][1], am[mi], b1);
                fma2(acc[mi][2], am[mi], b2);
                fma2(acc[mi][3], am[mi], b3);
            }
        }
        __syncthreads();
    }
    #pragma unroll
    for (int mi = 0; mi < 8; mi++) {
        int m = m0 + ty4 + (mi & 3) + ((mi >> 2) << 6);
        u64 bv = bc2(bias[m]);
        float* crow = Cb + (size_t)m * N + n0;
        u64 r0 = add2(acc[mi][0], bv), r1 = add2(acc[mi][1], bv);
        u64 r2 = add2(acc[mi][2], bv), r3 = add2(acc[mi][3], bv);
        *(u64*)(crow + tx4) = r0;      *(u64*)(crow + tx4 + 2) = r1;
        *(u64*)(crow + 64 + tx4) = r2; *(u64*)(crow + 64 + tx4 + 2) = r3;
    }
}

__global__ __launch_bounds__(256) void gemm_qkv_kernel(const float* __restrict__ x) {
    gemm128_body(g_wqkv, x, g_bqkv, g_qkv, DIMC);
}
__global__ __launch_bounds__(256) void gemm_proj_kernel(float* __restrict__ out) {
    gemm128_body(g_wproj, g_y, g_bproj, out, DIMC);
}

// ---------------- flash attention (128q x 128k tiles, f32x2) ----------------
// smem floats: sQ 32*128 | sK 32*128 | sV 128*72 (d + 4*(d>>5)) | sP 128*132
//              (j groups at col 0 and 68) | row_m/row_l/corr 128 each
#define SQ_OFF   0
#define SK_OFF   4096
#define SV_OFF   8192
#define SP_OFF   17408
#define STAT_OFF 34304
#define ATTN_SMEM_FLOATS 34688

__global__ __launch_bounds__(256) void attn_kernel()
{
    extern __shared__ float sm[];
    float* sQ = sm + SQ_OFF;
    float* sK = sm + SK_OFF;
    float* sV = sm + SV_OFF;
    float* sP = sm + SP_OFF;
    float* row_m = sm + STAT_OFF;
    float* row_l = row_m + 128;
    float* corr  = row_l + 128;

    const float scale = 0.17677669529663687f;   // KEY_DIM^-0.5
    int ib = blockIdx.x * 128;
    int head = blockIdx.y;
    int b = blockIdx.z;
    const float* base = g_qkv + (size_t)(b * HEADS + head) * 128 * NPIX;
    const float* Qg = base;
    const float* Kg = base + 32 * NPIX;
    const float* Vg = base + 64 * NPIX;

    int tid = threadIdx.x;
    int tx = tid & 15, ty = tid >> 4;
    int tx4 = tx * 4, ty4 = ty * 4;
    int dx = tx & 7, jg = tx >> 3;

    int jl0 = tid & 127, r0 = tid >> 7;

    {   // Q tile [d 0..31][i 0..127]
        #pragma unroll
        for (int r = 0; r < 16; r++) {
            int d = (r << 1) + r0;
            sQ[d * 128 + jl0] = Qg[(size_t)d * NPIX + ib + jl0];
        }
    }
    if (tid < 128) { row_m[tid] = -1e30f; row_l[tid] = 0.f; }

    u64 o[8][4];
    #pragma unroll
    for (int i = 0; i < 8; i++)
        #pragma unroll
        for (int j = 0; j < 4; j++) o[i][j] = 0ull;
    __syncthreads();

    int irow[8];
    #pragma unroll
    for (int ii = 0; ii < 8; ii++) irow[ii] = ty4 + (ii & 3) + ((ii >> 2) << 6);

    for (int jb = 0; jb < NPIX; jb += 128) {
        {   // K tile [d][j]
            #pragma unroll
            for (int r = 0; r < 16; r++) {
                int d = (r << 1) + r0;
                sK[d * 128 + jl0] = Kg[(size_t)d * NPIX + jb + jl0];
            }
            // V tile transposed: sV[j][d + 4*(d>>5)], pitch 72
            #pragma unroll
            for (int r = 0; r < 32; r++) {
                int d = (r << 1) + r0;
                sV[jl0 * 72 + d + ((d >> 5) << 2)] = Vg[(size_t)d * NPIX + jb + jl0];
            }
        }
        __syncthreads();

        // ---- S = Q^T K (raw scores; scale folded into exp) ----
        u64 s2[8][4];
        #pragma unroll
        for (int i = 0; i < 8; i++)
            #pragma unroll
            for (int j = 0; j < 4; j++) s2[i][j] = 0ull;

        #pragma unroll 8
        for (int d = 0; d < 32; d++) {
            const float* qrow = sQ + d * 128;
            const float* krow = sK + d * 128;
            float4 qa = *(const float4*)(qrow + ty4);
            float4 qb = *(const float4*)(qrow + 64 + ty4);
            u64 k0 = *(const u64*)(krow + tx4);
            u64 k1 = *(const u64*)(krow + tx4 + 2);
            u64 k2 = *(const u64*)(krow + 64 + tx4);
            u64 k3 = *(const u64*)(krow + 64 + tx4 + 2);
            u64 q[8] = {bc2(qa.x), bc2(qa.y), bc2(qa.z), bc2(qa.w),
                        bc2(qb.x), bc2(qb.y), bc2(qb.z), bc2(qb.w)};
            #pragma unroll
            for (int ii = 0; ii < 8; ii++) {
                fma2(s2[ii][0], q[ii], k0);
                fma2(s2[ii][1], q[ii], k1);
                fma2(s2[ii][2], q[ii], k2);
                fma2(s2[ii][3], q[ii], k3);
            }
        }
        #pragma unroll
        for (int ii = 0; ii < 8; ii++) {
            float* pr = sP + irow[ii] * 132;
            *(u64*)(pr + tx4) = s2[ii][0];
            *(u64*)(pr + tx4 + 2) = s2[ii][1];
            *(u64*)(pr + 68 + tx4) = s2[ii][2];
            *(u64*)(pr + 68 + tx4 + 2) = s2[ii][3];
        }
        __syncthreads();

        // ---- online softmax: 2 threads per row ----
        {
            int r = tid >> 1, p = tid & 1;
            float* row = sP + r * 132 + p * 68;
            float mx = -1e30f;
            #pragma unroll 8
            for (int c = 0; c < 64; c += 4) {
                float4 v = *(const float4*)(row + c);
                mx = fmaxf(mx, fmaxf(fmaxf(v.x, v.y), fmaxf(v.z, v.w)));
            }
            mx = fmaxf(mx, __shfl_xor_sync(0xffffffffu, mx, 1));
            float m_old = row_m[r];
            float m_new = fmaxf(m_old, mx);
            float ls = 0.f;
            #pragma unroll 8
            for (int c = 0; c < 64; c += 4) {
                float4 v = *(float4*)(row + c);
                v.x = __expf((v.x - m_new) * scale);
                v.y = __expf((v.y - m_new) * scale);
                v.z = __expf((v.z - m_new) * scale);
                v.w = __expf((v.w - m_new) * scale);
                *(float4*)(row + c) = v;
                ls += v.x + v.y + v.z + v.w;
            }
            ls += __shfl_xor_sync(0xffffffffu, ls, 1);
            if (p == 0) {
                float cf = __expf((m_old - m_new) * scale);
                corr[r] = cf;
                row_l[r] = row_l[r] * cf + ls;
                row_m[r] = m_new;
            }
        }
        __syncthreads();

        // ---- O += P V  (each thread: its jg half of j) ----
        #pragma unroll
        for (int ii = 0; ii < 8; ii++) {
            u64 c2 = bc2(corr[irow[ii]]);
            mul2(o[ii][0], c2); mul2(o[ii][1], c2);
            mul2(o[ii][2], c2); mul2(o[ii][3], c2);
        }
        {
            int vbase = dx * 8 + ((dx >> 2) << 2);
            int joff = jg * 68;
            int vrow0 = jg * 64;
            #pragma unroll 2
            for (int jl = 0; jl < 64; jl += 4) {
                float4 p4[8];
                #pragma unroll
                for (int ii = 0; ii < 8; ii++)
                    p4[ii] = *(const float4*)(sP + irow[ii] * 132 + joff + jl);
                #pragma unroll
                for (int t = 0; t < 4; t++) {
                    const float* vr = sV + (vrow0 + jl + t) * 72 + vbase;
                    u64 v0 = *(const u64*)(vr);
                    u64 v1 = *(const u64*)(vr + 2);
                    u64 v2 = *(const u64*)(vr + 4);
                    u64 v3 = *(const u64*)(vr + 6);
                    #pragma unroll
                    for (int ii = 0; ii < 8; ii++) {
                        float pa[4] = {p4[ii].x, p4[ii].y, p4[ii].z, p4[ii].w};
                        u64 pb = bc2(pa[t]);
                        fma2(o[ii][0], pb, v0);
                        fma2(o[ii][1], pb, v1);
                        fma2(o[ii][2], pb, v2);
                        fma2(o[ii][3], pb, v3);
                    }
                }
            }
        }
        __syncthreads();
    }

    // ---- reduce jg halves (lanes 8 apart), normalize, stage, store ----
    #pragma unroll
    for (int ii = 0; ii < 8; ii++)
        #pragma unroll
        for (int dp = 0; dp < 4; dp++) {
            u64 other = __shfl_xor_sync(0xffffffffu, o[ii][dp], 8);
            o[ii][dp] = add2(o[ii][dp], other);
        }

    float* stage = sm;   // reuse sQ+sK region: 64 x 128
    if (jg == 0) {
        #pragma unroll
        for (int ii = 0; ii < 8; ii++) {
            u64 il = bc2(1.f / row_l[irow[ii]]);
            #pragma unroll
            for (int dp = 0; dp < 4; dp++) {
                mul2(o[ii][dp], il);
                float lo, hi;
                up2(o[ii][dp], lo, hi);
                int d = dx * 8 + dp * 2;
                stage[d * 128 + irow[ii]] = lo;
                stage[(d + 1) * 128 + irow[ii]] = hi;
            }
        }
    }
    __syncthreads();
    {
        float* yout = g_y + ((size_t)b * DIMC + head * 64) * NPIX + ib;
        #pragma unroll
        for (int r = 0; r < 32; r++) {
            int d = (r << 1) + r0;
            yout[(size_t)d * NPIX + jl0] = stage[d * 128 + jl0];
        }
    }
}

// ---------------- depthwise 3x3 pe conv + residual add ---------------------
__global__ __launch_bounds__(256) void pe_add_kernel()
{
    int idx = blockIdx.x * 256 + threadIdx.x;
    if (idx >= NB * DIMC * NPIX) return;
    int n = idx & 4095;
    int c = (idx >> 12) & 255;
    int b = idx >> 20;
    int hh = n >> 6, ww = n & 63;
    int head = c >> 6, dv = c & 63;
    const float* V = g_qkv + ((size_t)(b * HEADS + head) * 128 + 64 + dv) * NPIX;
    const float* w = g_wpe + c * 9;
    float s = g_bpe[c];
    #pragma unroll
    for (int ky = -1; ky <= 1; ky++) {
        int yy = hh + ky;
        if (yy < 0 || yy > 63) continue;
        #pragma unroll
        for (int kx = -1; kx <= 1; kx++) {
            int xx = ww + kx;
            if (xx < 0 || xx > 63) continue;
            s = fmaf(w[(ky + 1) * 3 + kx + 1], V[yy * 64 + xx], s);
        }
    }
    g_y[idx] += s;
}

// ---------------- launch ----------------------------------------------------
extern "C" void kernel_launch(void* const* d_in, const int* in_sizes, int n_in,
                              void* d_out, int out_size)
{
    const float* x = (const float*)d_in[0];

    // Host-side, non-stream, idempotent; legal during graph capture.
    cudaFuncSetAttribute(attn_kernel, cudaFuncAttributeMaxDynamicSharedMemorySize,
                         ATTN_SMEM_FLOATS * 4);

    fold_kernel<<<64, 256>>>(
        (const float*)d_in[1], (const float*)d_in[2], (const float*)d_in[3],
        (const float*)d_in[4], (const float*)d_in[5],
        (const float*)d_in[6], (const float*)d_in[7], (const float*)d_in[8],
        (const float*)d_in[9], (const float*)d_in[10],
        (const float*)d_in[11], (const float*)d_in[12], (const float*)d_in[13],
        (const float*)d_in[14], (const float*)d_in[15]);

    dim3 gq(NPIX / 128, HIDDEN / 128, NB);
    gemm_qkv_kernel<<<gq, 256>>>(x);

    dim3 ga(NPIX / 128, HEADS, NB);
    attn_kernel<<<ga, 256, ATTN_SMEM_FLOATS * 4>>>();

    pe_add_kernel<<<(NB * DIMC * NPIX) / 256, 256>>>();

    dim3 gp(NPIX / 128, DIMC / 128, NB);
    gemm_proj_kernel<<<gp, 256>>>((float*)d_out);
}

// round 8
// speedup vs baseline: 2.0826x; 1.0229x over previous
#include <cuda_runtime.h>
#include <cuda_bf16.h>
#include <cstdint>

#define DIMC 256
#define HEADS 4
#define HEAD_DIM 64
#define KEY_DIM 32
#define HIDDEN 512
#define NB 2
#define NPIX 4096
#define EPS 1e-5f

typedef unsigned long long u64;

// ---------------- packed f32x2 helpers (GEMM path) --------------------------
__device__ __forceinline__ u64 pk2(float lo, float hi) {
    u64 r; asm("mov.b64 %0, {%1, %2};" : "=l"(r) : "f"(lo), "f"(hi)); return r;
}
__device__ __forceinline__ u64 bc2(float v) { return pk2(v, v); }
__device__ __forceinline__ void fma2(u64& d, u64 a, u64 b) {
    asm("fma.rn.f32x2 %0, %1, %2, %0;" : "+l"(d) : "l"(a), "l"(b));
}
__device__ __forceinline__ u64 add2(u64 a, u64 b) {
    u64 r; asm("add.rn.f32x2 %0, %1, %2;" : "=l"(r) : "l"(a), "l"(b)); return r;
}

// ---------------- mma.sync helper (base-target HMMA, fp32 accum) ------------
__device__ __forceinline__ void mma16816(float* d, const uint32_t* a, const uint32_t* b) {
    asm volatile(
        "mma.sync.aligned.m16n8k16.row.col.f32.bf16.bf16.f32 "
        "{%0,%1,%2,%3}, {%4,%5,%6,%7}, {%8,%9}, {%0,%1,%2,%3};"
        : "+f"(d[0]), "+f"(d[1]), "+f"(d[2]), "+f"(d[3])
        : "r"(a[0]), "r"(a[1]), "r"(a[2]), "r"(a[3]), "r"(b[0]), "r"(b[1]));
}

// ---------------- scratch ---------------------------------------------------
__device__ float g_qkv[NB * HIDDEN * NPIX];
__device__ float g_y[NB * DIMC * NPIX];
__device__ float g_wqkv[HIDDEN * DIMC];
__device__ float g_bqkv[HIDDEN];
__device__ float g_wproj[DIMC * DIMC];
__device__ float g_bproj[DIMC];
__device__ float g_wpe[DIMC * 9];
__device__ float g_bpe[DIMC];

// ---------------- fold BN into conv weights --------------------------------
__global__ void fold_kernel(
    const float* __restrict__ qkv_w, const float* __restrict__ qkv_g, const float* __restrict__ qkv_b,
    const float* __restrict__ qkv_m, const float* __restrict__ qkv_v,
    const float* __restrict__ proj_w, const float* __restrict__ proj_g, const float* __restrict__ proj_b,
    const float* __restrict__ proj_m, const float* __restrict__ proj_v,
    const float* __restrict__ pe_w, const float* __restrict__ pe_g, const float* __restrict__ pe_b,
    const float* __restrict__ pe_m, const float* __restrict__ pe_v)
{
    int stride = gridDim.x * blockDim.x;
    int t0 = blockIdx.x * blockDim.x + threadIdx.x;
    for (int i = t0; i < HIDDEN * DIMC; i += stride) {
        int o = i >> 8;
        g_wqkv[i] = qkv_w[i] * (qkv_g[o] * rsqrtf(qkv_v[o] + EPS));
    }
    for (int i = t0; i < DIMC * DIMC; i += stride) {
        int o = i >> 8;
        g_wproj[i] = proj_w[i] * (proj_g[o] * rsqrtf(proj_v[o] + EPS));
    }
    for (int i = t0; i < DIMC * 9; i += stride) {
        int c = i / 9;
        g_wpe[i] = pe_w[i] * (pe_g[c] * rsqrtf(pe_v[c] + EPS));
    }
    for (int i = t0; i < HIDDEN; i += stride) {
        float s = qkv_g[i] * rsqrtf(qkv_v[i] + EPS);
        g_bqkv[i] = qkv_b[i] - qkv_m[i] * s;
    }
    for (int i = t0; i < DIMC; i += stride) {
        float s = proj_g[i] * rsqrtf(proj_v[i] + EPS);
        g_bproj[i] = proj_b[i] - proj_m[i] * s;
        float sp = pe_g[i] * rsqrtf(pe_v[i] + EPS);
        g_bpe[i] = pe_b[i] - pe_m[i] * sp;
    }
}

// ---------------- 128x128 f32x2 GEMM with fused bias ------------------------
__device__ __forceinline__ void gemm128_body(
    const float* __restrict__ A, const float* __restrict__ X,
    const float* __restrict__ bias, float* __restrict__ C, int K)
{
    const int N = NPIX;
    int batch = blockIdx.z;
    const float* Xb = X + (size_t)batch * K * N;
    float* Cb = C + (size_t)batch * ((size_t)gridDim.y * 128) * N;
    int m0 = blockIdx.y * 128, n0 = blockIdx.x * 128;

    __shared__ float As[16][132];
    __shared__ float Bs[16][128];

    int tid = threadIdx.x;
    int tx = tid & 15, ty = tid >> 4;
    int tx4 = tx * 4, ty4 = ty * 4;

    u64 acc[8][4];
    #pragma unroll
    for (int i = 0; i < 8; i++)
        #pragma unroll
        for (int j = 0; j < 4; j++) acc[i][j] = 0ull;

    int mrow = tid >> 1, kq = (tid & 1) * 8;

    for (int k0 = 0; k0 < K; k0 += 16) {
        float4 a0 = *(const float4*)&A[(size_t)(m0 + mrow) * K + k0 + kq];
        float4 a1 = *(const float4*)&A[(size_t)(m0 + mrow) * K + k0 + kq + 4];
        As[kq + 0][mrow] = a0.x; As[kq + 1][mrow] = a0.y;
        As[kq + 2][mrow] = a0.z; As[kq + 3][mrow] = a0.w;
        As[kq + 4][mrow] = a1.x; As[kq + 5][mrow] = a1.y;
        As[kq + 6][mrow] = a1.z; As[kq + 7][mrow] = a1.w;
        #pragma unroll
        for (int r = 0; r < 8; r++) {
            int idx = r * 256 + tid;
            int nn = idx & 127, kk = idx >> 7;
            Bs[kk][nn] = Xb[(size_t)(k0 + kk) * N + n0 + nn];
        }
        __syncthreads();
        #pragma unroll
        for (int kk = 0; kk < 16; kk++) {
            float4 qa = *(const float4*)&As[kk][ty4];
            float4 qb = *(const float4*)&As[kk][64 + ty4];
            u64 b0 = *(const u64*)&Bs[kk][tx4];
            u64 b1 = *(const u64*)&Bs[kk][tx4 + 2];
            u64 b2 = *(const u64*)&Bs[kk][64 + tx4];
            u64 b3 = *(const u64*)&Bs[kk][64 + tx4 + 2];
            u64 am[8] = {bc2(qa.x), bc2(qa.y), bc2(qa.z), bc2(qa.w),
                         bc2(qb.x), bc2(qb.y), bc2(qb.z), bc2(qb.w)};
            #pragma unroll
            for (int mi = 0; mi < 8; mi++) {
                fma2(acc[mi][0], am[mi], b0);
                fma2(acc[mi][1], am[mi], b1);
                fma2(acc[mi][2], am[mi], b2);
                fma2(acc[mi][3], am[mi], b3);
            }
        }
        __syncthreads();
    }
    #pragma unroll
    for (int mi = 0; mi < 8; mi++) {
        int m = m0 + ty4 + (mi & 3) + ((mi >> 2) << 6);
        u64 bv = bc2(bias[m]);
        float* crow = Cb + (size_t)m * N + n0;
        u64 r0 = add2(acc[mi][0], bv), r1 = add2(acc[mi][1], bv);
        u64 r2 = add2(acc[mi][2], bv), r3 = add2(acc[mi][3], bv);
        *(u64*)(crow + tx4) = r0;      *(u64*)(crow + tx4 + 2) = r1;
        *(u64*)(crow + 64 + tx4) = r2; *(u64*)(crow + 64 + tx4 + 2) = r3;
    }
}

__global__ __launch_bounds__(256) void gemm_qkv_kernel(const float* __restrict__ x) {
    gemm128_body(g_wqkv, x, g_bqkv, g_qkv, DIMC);
}
__global__ __launch_bounds__(256) void gemm_proj_kernel(float* __restrict__ out) {
    gemm128_body(g_wproj, g_y, g_bproj, out, DIMC);
}

// ---------------- mma.sync flash attention ----------------------------------
// Layouts (byte offsets into dynamic smem):
//  Q: [i 0..127][144B row]: hi bf16 at 2d, lo bf16 at 64+2d       (18432 B)
//  K: same, rows = keys                                            (18432 B)
//  Vh/Vl: [d 0..63][272B row]: bf16 at 2j                          (17408 B each)
//  S/P: [i 0..127][560B row]: raw S fp32 cols*4;
//       after softmax: P hi bf16-pairs at bytes [0,256), lo at [280,536)
//  stats: row_m / row_l / corr (128 f each)
#define PQK 144
#define PVROW 272
#define PSROW 560
#define Q_OFF 0
#define K_OFF 18432
#define VH_OFF 36864
#define VL_OFF 54272
#define S_OFF 71680
#define STAT_OFF 143360
#define ATTN_SMEM 144896

__global__ __launch_bounds__(256, 1) void attn_mma_kernel()
{
    extern __shared__ char sb[];
    float* row_m = (float*)(sb + STAT_OFF);
    float* row_l = row_m + 128;
    float* corr  = row_l + 128;

    const float scale = 0.17677669529663687f;   // KEY_DIM^-0.5
    int ib = blockIdx.x * 128, head = blockIdx.y, b = blockIdx.z;
    const float* base = g_qkv + (size_t)(b * HEADS + head) * 128 * NPIX;
    const float* Qg = base;
    const float* Kg = base + 32 * NPIX;
    const float* Vg = base + 64 * NPIX;

    int tid = threadIdx.x, wid = tid >> 5, lid = tid & 31;
    int g = lid >> 2;            // fragment row group
    int c4 = (lid & 3) * 4;      // byte offset of this thread's k-pair

    // ---- persistent Q tile (hi/lo split) ----
    for (int f = tid; f < 4096; f += 256) {
        int d = f >> 7, i = f & 127;
        float x = Qg[(size_t)d * NPIX + ib + i];
        __nv_bfloat16 h = __float2bfloat16(x);
        __nv_bfloat16 l = __float2bfloat16(x - __bfloat162float(h));
        *(__nv_bfloat16*)(sb + Q_OFF + i * PQK + 2 * d) = h;
        *(__nv_bfloat16*)(sb + Q_OFF + i * PQK + 64 + 2 * d) = l;
    }
    if (tid < 128) { row_m[tid] = -1e30f; row_l[tid] = 0.f; }

    float oa[2][4][4];
    #pragma unroll
    for (int a = 0; a < 2; a++)
        #pragma unroll
        for (int bq = 0; bq < 4; bq++)
            #pragma unroll
            for (int e = 0; e < 4; e++) oa[a][bq][e] = 0.f;

    int swr = (wid >> 2) * 64, swc = (wid & 3) * 32;   // S-phase: 64x32 tile
    int pwr = (wid >> 1) * 32, pwc = (wid & 1) * 32;   // PV-phase: 32x32 tile
    __syncthreads();

    for (int jt = 0; jt < 32; jt++) {
        int jb = jt * 128;

        // ---- K / V tile loads (hi/lo split) ----
        for (int f = tid; f < 4096; f += 256) {
            int d = f >> 7, j = f & 127;
            float x = Kg[(size_t)d * NPIX + jb + j];
            __nv_bfloat16 h = __float2bfloat16(x);
            __nv_bfloat16 l = __float2bfloat16(x - __bfloat162float(h));
            *(__nv_bfloat16*)(sb + K_OFF + j * PQK + 2 * d) = h;
            *(__nv_bfloat16*)(sb + K_OFF + j * PQK + 64 + 2 * d) = l;
        }
        for (int f = tid; f < 8192; f += 256) {
            int d = f >> 7, j = f & 127;
            float x = Vg[(size_t)d * NPIX + jb + j];
            __nv_bfloat16 h = __float2bfloat16(x);
            __nv_bfloat16 l = __float2bfloat16(x - __bfloat162float(h));
            *(__nv_bfloat16*)(sb + VH_OFF + d * PVROW + 2 * j) = h;
            *(__nv_bfloat16*)(sb + VL_OFF + d * PVROW + 2 * j) = l;
        }
        __syncthreads();

        // ---- S = Q K^T  (3-term split, 2 k-steps of 16; term loop NOT unrolled) ----
        float sa[4][4][4];
        #pragma unroll
        for (int mi = 0; mi < 4; mi++)
            #pragma unroll
            for (int ni = 0; ni < 4; ni++)
                #pragma unroll
                for (int e = 0; e < 4; e++) sa[mi][ni][e] = 0.f;

        #pragma unroll 1
        for (int term = 0; term < 3; term++) {
            int aL = (term == 2) ? 64 : 0;
            int bL = (term == 1) ? 64 : 0;
            const char* aBase = sb + Q_OFF + (swr + g) * PQK + aL + c4;
            const char* bBase = sb + K_OFF + (swc + g) * PQK + bL + c4;
            #pragma unroll
            for (int ks = 0; ks < 2; ks++) {
                int kB = ks * 32;
                uint32_t afr[4][4], bfr[4][2];
                #pragma unroll
                for (int mi = 0; mi < 4; mi++) {
                    const char* ap = aBase + mi * 16 * PQK + kB;
                    afr[mi][0] = *(const uint32_t*)ap;
                    afr[mi][1] = *(const uint32_t*)(ap + 8 * PQK);
                    afr[mi][2] = *(const uint32_t*)(ap + 16);
                    afr[mi][3] = *(const uint32_t*)(ap + 8 * PQK + 16);
                }
                #pragma unroll
                for (int ni = 0; ni < 4; ni++) {
                    const char* bp = bBase + ni * 8 * PQK + kB;
                    bfr[ni][0] = *(const uint32_t*)bp;
                    bfr[ni][1] = *(const uint32_t*)(bp + 16);
                }
                #pragma unroll
                for (int mi = 0; mi < 4; mi++)
                    #pragma unroll
                    for (int ni = 0; ni < 4; ni++)
                        mma16816(sa[mi][ni], afr[mi], bfr[ni]);
            }
        }
        #pragma unroll
        for (int mi = 0; mi < 4; mi++)
            #pragma unroll
            for (int ni = 0; ni < 4; ni++) {
                int r = swr + mi * 16 + g;
                int colB = (swc + ni * 8) * 4 + c4 * 2;
                *(float2*)(sb + S_OFF + r * PSROW + colB) = make_float2(sa[mi][ni][0], sa[mi][ni][1]);
                *(float2*)(sb + S_OFF + (r + 8) * PSROW + colB) = make_float2(sa[mi][ni][2], sa[mi][ni][3]);
            }
        __syncthreads();

        // ---- online softmax: 2 threads per row; row half buffered in regs ----
        {
            int r = tid >> 1, p = tid & 1;
            const char* rowp = sb + S_OFF + r * PSROW + p * 256;
            float4 vbuf[16];
            #pragma unroll
            for (int q = 0; q < 16; q++) vbuf[q] = *(const float4*)(rowp + q * 16);
            float mx = -1e30f;
            #pragma unroll
            for (int q = 0; q < 16; q++) {
                float4 v = vbuf[q];
                mx = fmaxf(mx, fmaxf(fmaxf(v.x, v.y), fmaxf(v.z, v.w)));
            }
            mx = fmaxf(mx, __shfl_xor_sync(0xffffffffu, mx, 1));
            float m_old = row_m[r];
            float m_new = fmaxf(m_old, mx);
            float ls = 0.f;
            char* hip = sb + S_OFF + r * PSROW + p * 128;
            char* lop = sb + S_OFF + r * PSROW + 280 + p * 128;
            #pragma unroll 4
            for (int q = 0; q < 16; q++) {
                float4 v = vbuf[q];
                float p0 = __expf((v.x - m_new) * scale);
                float p1 = __expf((v.y - m_new) * scale);
                float p2 = __expf((v.z - m_new) * scale);
                float p3 = __expf((v.w - m_new) * scale);
                ls += (p0 + p1) + (p2 + p3);
                __nv_bfloat16 h0 = __float2bfloat16(p0), h1 = __float2bfloat16(p1);
                __nv_bfloat16 h2 = __float2bfloat16(p2), h3 = __float2bfloat16(p3);
                __nv_bfloat162 hw0; hw0.x = h0; hw0.y = h1;
                __nv_bfloat162 hw1; hw1.x = h2; hw1.y = h3;
                *(uint32_t*)(hip + q * 8)     = *(uint32_t*)&hw0;
                *(uint32_t*)(hip + q * 8 + 4) = *(uint32_t*)&hw1;
                __nv_bfloat162 lw0, lw1;
                lw0.x = __float2bfloat16(p0 - __bfloat162float(h0));
                lw0.y = __float2bfloat16(p1 - __bfloat162float(h1));
                lw1.x = __float2bfloat16(p2 - __bfloat162float(h2));
                lw1.y = __float2bfloat16(p3 - __bfloat162float(h3));
                *(uint32_t*)(lop + q * 8)     = *(uint32_t*)&lw0;
                *(uint32_t*)(lop + q * 8 + 4) = *(uint32_t*)&lw1;
            }
            ls += __shfl_xor_sync(0xffffffffu, ls, 1);
            if (p == 0) {
                float cf = __expf((m_old - m_new) * scale);
                corr[r] = cf;
                row_l[r] = row_l[r] * cf + ls;
                row_m[r] = m_new;
            }
        }
        __syncthreads();

        // ---- O = O*corr + P V^T (3-term split, 8 k-steps; term loop NOT unrolled) ----
        #pragma unroll
        for (int mi = 0; mi < 2; mi++) {
            float c0 = corr[pwr + mi * 16 + g];
            float c1 = corr[pwr + mi * 16 + g + 8];
            #pragma unroll
            for (int ni = 0; ni < 4; ni++) {
                oa[mi][ni][0] *= c0; oa[mi][ni][1] *= c0;
                oa[mi][ni][2] *= c1; oa[mi][ni][3] *= c1;
            }
        }
        #pragma unroll 1
        for (int term = 0; term < 3; term++) {
            int aL = (term == 2) ? 280 : 0;
            const char* vBase = sb + ((term == 1) ? VL_OFF : VH_OFF) + (pwc + g) * PVROW + c4;
            const char* pBase = sb + S_OFF + (pwr + g) * PSROW + aL + c4;
            #pragma unroll 2
            for (int ks = 0; ks < 8; ks++) {
                int kB = ks * 32;
                uint32_t afr[2][4], bfr[4][2];
                #pragma unroll
                for (int mi = 0; mi < 2; mi++) {
                    const char* ap = pBase + mi * 16 * PSROW + kB;
                    afr[mi][0] = *(const uint32_t*)ap;
                    afr[mi][1] = *(const uint32_t*)(ap + 8 * PSROW);
                    afr[mi][2] = *(const uint32_t*)(ap + 16);
                    afr[mi][3] = *(const uint32_t*)(ap + 8 * PSROW + 16);
                }
                #pragma unroll
                for (int ni = 0; ni < 4; ni++) {
                    const char* bp = vBase + ni * 8 * PVROW + kB;
                    bfr[ni][0] = *(const uint32_t*)bp;
                    bfr[ni][1] = *(const uint32_t*)(bp + 16);
                }
                #pragma unroll
                for (int mi = 0; mi < 2; mi++)
                    #pragma unroll
                    for (int ni = 0; ni < 4; ni++)
                        mma16816(oa[mi][ni], afr[mi], bfr[ni]);
            }
        }
        __syncthreads();
    }

    // ---- epilogue: normalize, transpose via smem stage, store -------------
    float* stage = (float*)sb;   // 64 x 132 floats, overlays Q/K (dead now)
    #pragma unroll
    for (int mi = 0; mi < 2; mi++) {
        int r0 = pwr + mi * 16 + g;
        float i0 = 1.f / row_l[r0];
        float i1 = 1.f / row_l[r0 + 8];
        #pragma unroll
        for (int ni = 0; ni < 4; ni++) {
            int d0 = pwc + ni * 8 + (c4 >> 1);
            stage[d0 * 132 + r0]       = oa[mi][ni][0] * i0;
            stage[(d0 + 1) * 132 + r0] = oa[mi][ni][1] * i0;
            stage[d0 * 132 + r0 + 8]       = oa[mi][ni][2] * i1;
            stage[(d0 + 1) * 132 + r0 + 8] = oa[mi][ni][3] * i1;
        }
    }
    __syncthreads();
    {
        float* yout = g_y + ((size_t)b * DIMC + head * 64) * NPIX + ib;
        for (int f = tid; f < 8192; f += 256) {
            int d = f >> 7, i = f & 127;
            yout[(size_t)d * NPIX + i] = stage[d * 132 + i];
        }
    }
}

// ---------------- depthwise 3x3 pe conv + residual add ---------------------
__global__ __launch_bounds__(256) void pe_add_kernel()
{
    int idx = blockIdx.x * 256 + threadIdx.x;
    if (idx >= NB * DIMC * NPIX) return;
    int n = idx & 4095;
    int c = (idx >> 12) & 255;
    int b = idx >> 20;
    int hh = n >> 6, ww = n & 63;
    int head = c >> 6, dv = c & 63;
    const float* V = g_qkv + ((size_t)(b * HEADS + head) * 128 + 64 + dv) * NPIX;
    const float* w = g_wpe + c * 9;
    float s = g_bpe[c];
    #pragma unroll
    for (int ky = -1; ky <= 1; ky++) {
        int yy = hh + ky;
        if (yy < 0 || yy > 63) continue;
        #pragma unroll
        for (int kx = -1; kx <= 1; kx++) {
            int xx = ww + kx;
            if (xx < 0 || xx > 63) continue;
            s = fmaf(w[(ky + 1) * 3 + kx + 1], V[yy * 64 + xx], s);
        }
    }
    g_y[idx] += s;
}

// ---------------- launch ----------------------------------------------------
extern "C" void kernel_launch(void* const* d_in, const int* in_sizes, int n_in,
                              void* d_out, int out_size)
{
    const float* x = (const float*)d_in[0];

    cudaFuncSetAttribute(attn_mma_kernel, cudaFuncAttributeMaxDynamicSharedMemorySize,
                         ATTN_SMEM);

    fold_kernel<<<64, 256>>>(
        (const float*)d_in[1], (const float*)d_in[2], (const float*)d_in[3],
        (const float*)d_in[4], (const float*)d_in[5],
        (const float*)d_in[6], (const float*)d_in[7], (const float*)d_in[8],
        (const float*)d_in[9], (const float*)d_in[10],
        (const float*)d_in[11], (const float*)d_in[12], (const float*)d_in[13],
        (const float*)d_in[14], (const float*)d_in[15]);

    dim3 gq(NPIX / 128, HIDDEN / 128, NB);
    gemm_qkv_kernel<<<gq, 256>>>(x);

    dim3 ga(NPIX / 128, HEADS, NB);
    attn_mma_kernel<<<ga, 256, ATTN_SMEM>>>();

    pe_add_kernel<<<(NB * DIMC * NPIX) / 256, 256>>>();

    dim3 gp(NPIX / 128, DIMC / 128, NB);
    gemm_proj_kernel<<<gp, 256>>>((float*)d_out);
}

// round 11
// speedup vs baseline: 2.7442x; 1.3177x over previous
#include <cuda_runtime.h>
#include <cuda_bf16.h>
#include <cstdint>

#define DIMC 256
#define HEADS 4
#define HEAD_DIM 64
#define KEY_DIM 32
#define HIDDEN 512
#define NB 2
#define NPIX 4096
#define EPS 1e-5f

typedef unsigned long long u64;

// ---------------- packed f32x2 helpers (GEMM path) --------------------------
__device__ __forceinline__ u64 pk2(float lo, float hi) {
    u64 r; asm("mov.b64 %0, {%1, %2};" : "=l"(r) : "f"(lo), "f"(hi)); return r;
}
__device__ __forceinline__ u64 bc2(float v) { return pk2(v, v); }
__device__ __forceinline__ void fma2(u64& d, u64 a, u64 b) {
    asm("fma.rn.f32x2 %0, %1, %2, %0;" : "+l"(d) : "l"(a), "l"(b));
}
__device__ __forceinline__ u64 add2(u64 a, u64 b) {
    u64 r; asm("add.rn.f32x2 %0, %1, %2;" : "=l"(r) : "l"(a), "l"(b)); return r;
}

// ---------------- mma.sync helper (base-target HMMA, fp32 accum) ------------
__device__ __forceinline__ void mma16816(float* d, const uint32_t* a, const uint32_t* b) {
    asm volatile(
        "mma.sync.aligned.m16n8k16.row.col.f32.bf16.bf16.f32 "
        "{%0,%1,%2,%3}, {%4,%5,%6,%7}, {%8,%9}, {%0,%1,%2,%3};"
        : "+f"(d[0]), "+f"(d[1]), "+f"(d[2]), "+f"(d[3])
        : "r"(a[0]), "r"(a[1]), "r"(a[2]), "r"(a[3]), "r"(b[0]), "r"(b[1]));
}

// ---------------- scratch ---------------------------------------------------
__device__ float g_qkv[NB * HIDDEN * NPIX];
__device__ float g_y[NB * DIMC * NPIX];
__device__ float g_wqkv[HIDDEN * DIMC];
__device__ float g_bqkv[HIDDEN];
__device__ float g_wproj[DIMC * DIMC];
__device__ float g_bproj[DIMC];
__device__ float g_wpe[DIMC * 9];
__device__ float g_bpe[DIMC];
// pre-converted split-bf16 Q/K/V, laid out as attention smem tiles expect:
//  g_qc/g_kc: [bh][token][64] : hi bf16 of d at +d, lo at +32+d  (128B rows)
//  g_vc:      [bh][jt][v(hi/lo)][d 0..63][j 0..127]               (16KB blocks)
__device__ __nv_bfloat16 g_qc[NB * HEADS * NPIX * 64];
__device__ __nv_bfloat16 g_kc[NB * HEADS * NPIX * 64];
__device__ __nv_bfloat16 g_vc[NB * HEADS * 32 * 2 * 8192];

// ---------------- fold BN into conv weights --------------------------------
__global__ void fold_kernel(
    const float* __restrict__ qkv_w, const float* __restrict__ qkv_g, const float* __restrict__ qkv_b,
    const float* __restrict__ qkv_m, const float* __restrict__ qkv_v,
    const float* __restrict__ proj_w, const float* __restrict__ proj_g, const float* __restrict__ proj_b,
    const float* __restrict__ proj_m, const float* __restrict__ proj_v,
    const float* __restrict__ pe_w, const float* __restrict__ pe_g, const float* __restrict__ pe_b,
    const float* __restrict__ pe_m, const float* __restrict__ pe_v)
{
    int stride = gridDim.x * blockDim.x;
    int t0 = blockIdx.x * blockDim.x + threadIdx.x;
    for (int i = t0; i < HIDDEN * DIMC; i += stride) {
        int o = i >> 8;
        g_wqkv[i] = qkv_w[i] * (qkv_g[o] * rsqrtf(qkv_v[o] + EPS));
    }
    for (int i = t0; i < DIMC * DIMC; i += stride) {
        int o = i >> 8;
        g_wproj[i] = proj_w[i] * (proj_g[o] * rsqrtf(proj_v[o] + EPS));
    }
    for (int i = t0; i < DIMC * 9; i += stride) {
        int c = i / 9;
        g_wpe[i] = pe_w[i] * (pe_g[c] * rsqrtf(pe_v[c] + EPS));
    }
    for (int i = t0; i < HIDDEN; i += stride) {
        float s = qkv_g[i] * rsqrtf(qkv_v[i] + EPS);
        g_bqkv[i] = qkv_b[i] - qkv_m[i] * s;
    }
    for (int i = t0; i < DIMC; i += stride) {
        float s = proj_g[i] * rsqrtf(proj_v[i] + EPS);
        g_bproj[i] = proj_b[i] - proj_m[i] * s;
        float sp = pe_g[i] * rsqrtf(pe_v[i] + EPS);
        g_bpe[i] = pe_b[i] - pe_m[i] * sp;
    }
}

// ---------------- 128x128 f32x2 GEMM with fused bias ------------------------
__device__ __forceinline__ void gemm128_body(
    const float* __restrict__ A, const float* __restrict__ X,
    const float* __restrict__ bias, float* __restrict__ C, int K)
{
    const int N = NPIX;
    int batch = blockIdx.z;
    const float* Xb = X + (size_t)batch * K * N;
    float* Cb = C + (size_t)batch * ((size_t)gridDim.y * 128) * N;
    int m0 = blockIdx.y * 128, n0 = blockIdx.x * 128;

    __shared__ float As[16][132];
    __shared__ float Bs[16][128];

    int tid = threadIdx.x;
    int tx = tid & 15, ty = tid >> 4;
    int tx4 = tx * 4, ty4 = ty * 4;

    u64 acc[8][4];
    #pragma unroll
    for (int i = 0; i < 8; i++)
        #pragma unroll
        for (int j = 0; j < 4; j++) acc[i][j] = 0ull;

    int mrow = tid >> 1, kq = (tid & 1) * 8;

    for (int k0 = 0; k0 < K; k0 += 16) {
        float4 a0 = *(const float4*)&A[(size_t)(m0 + mrow) * K + k0 + kq];
        float4 a1 = *(const float4*)&A[(size_t)(m0 + mrow) * K + k0 + kq + 4];
        As[kq + 0][mrow] = a0.x; As[kq + 1][mrow] = a0.y;
        As[kq + 2][mrow] = a0.z; As[kq + 3][mrow] = a0.w;
        As[kq + 4][mrow] = a1.x; As[kq + 5][mrow] = a1.y;
        As[kq + 6][mrow] = a1.z; As[kq + 7][mrow] = a1.w;
        #pragma unroll
        for (int r = 0; r < 8; r++) {
            int idx = r * 256 + tid;
            int nn = idx & 127, kk = idx >> 7;
            Bs[kk][nn] = Xb[(size_t)(k0 + kk) * N + n0 + nn];
        }
        __syncthreads();
        #pragma unroll
        for (int kk = 0; kk < 16; kk++) {
            float4 qa = *(const float4*)&As[kk][ty4];
            float4 qb = *(const float4*)&As[kk][64 + ty4];
            u64 b0 = *(const u64*)&Bs[kk][tx4];
            u64 b1 = *(const u64*)&Bs[kk][tx4 + 2];
            u64 b2 = *(const u64*)&Bs[kk][64 + tx4];
            u64 b3 = *(const u64*)&Bs[kk][64 + tx4 + 2];
            u64 am[8] = {bc2(qa.x), bc2(qa.y), bc2(qa.z), bc2(qa.w),
                         bc2(qb.x), bc2(qb.y), bc2(qb.z), bc2(qb.w)};
            #pragma unroll
            for (int mi = 0; mi < 8; mi++) {
                fma2(acc[mi][0], am[mi], b0);
                fma2(acc[mi][1], am[mi], b1);
                fma2(acc[mi][2], am[mi], b2);
                fma2(acc[mi][3], am[mi], b3);
            }
        }
        __syncthreads();
    }
    #pragma unroll
    for (int mi = 0; mi < 8; mi++) {
        int m = m0 + ty4 + (mi & 3) + ((mi >> 2) << 6);
        u64 bv = bc2(bias[m]);
        float* crow = Cb + (size_t)m * N + n0;
        u64 r0 = add2(acc[mi][0], bv), r1 = add2(acc[mi][1], bv);
        u64 r2 = add2(acc[mi][2], bv), r3 = add2(acc[mi][3], bv);
        *(u64*)(crow + tx4) = r0;      *(u64*)(crow + tx4 + 2) = r1;
        *(u64*)(crow + 64 + tx4) = r2; *(u64*)(crow + 64 + tx4 + 2) = r3;
    }
}

__global__ __launch_bounds__(256) void gemm_qkv_kernel(const float* __restrict__ x) {
    gemm128_body(g_wqkv, x, g_bqkv, g_qkv, DIMC);
}
__global__ __launch_bounds__(256) void gemm_proj_kernel(float* __restrict__ out) {
    gemm128_body(g_wproj, g_y, g_bproj, out, DIMC);
}

// ---------------- one-shot Q/K/V split-bf16 conversion ----------------------
__global__ __launch_bounds__(256) void qkv_convert_kernel()
{
    int jt = blockIdx.x, bh = blockIdx.y;
    int jb = jt * 128, tid = threadIdx.x;
    const float* base = g_qkv + (size_t)bh * 128 * NPIX;

    for (int f = tid; f < 4096; f += 256) {
        int d = f >> 7, j = f & 127;
        float xq = base[(size_t)d * NPIX + jb + j];
        float xk = base[(size_t)(32 + d) * NPIX + jb + j];
        __nv_bfloat16 qh = __float2bfloat16(xq);
        __nv_bfloat16 ql = __float2bfloat16(xq - __bfloat162float(qh));
        __nv_bfloat16 kh = __float2bfloat16(xk);
        __nv_bfloat16 kl = __float2bfloat16(xk - __bfloat162float(kh));
        size_t ro = ((size_t)bh * NPIX + jb + j) * 64 + d;
        g_qc[ro] = qh; g_qc[ro + 32] = ql;
        g_kc[ro] = kh; g_kc[ro + 32] = kl;
    }
    for (int f = tid; f < 8192; f += 256) {
        int d = f >> 7, j = f & 127;
        float x = base[(size_t)(64 + d) * NPIX + jb + j];
        __nv_bfloat16 h = __float2bfloat16(x);
        __nv_bfloat16 l = __float2bfloat16(x - __bfloat162float(h));
        size_t o = (size_t)(bh * 32 + jt) * 2 * 8192 + d * 128 + j;
        g_vc[o] = h;
        g_vc[o + 8192] = l;
    }
}

// ---------------- mma.sync flash attention ----------------------------------
// smem layouts (byte offsets): Q/K pitch 144 (hi at 2d, lo at 64+2d),
// Vh/Vl pitch 272, S/P pitch 560 (S fp32; P hi at [0,256), lo at [280,536))
#define PQK 144
#define PVROW 272
#define PSROW 560
#define Q_OFF 0
#define K_OFF 18432
#define VH_OFF 36864
#define VL_OFF 54272
#define S_OFF 71680
#define STAT_OFF 143360
#define ATTN_SMEM 144896

__global__ __launch_bounds__(256, 1) void attn_mma_kernel()
{
    extern __shared__ char sb[];
    float* row_m = (float*)(sb + STAT_OFF);
    float* row_l = row_m + 128;
    float* corr  = row_l + 128;

    const float scale = 0.17677669529663687f;   // KEY_DIM^-0.5
    int ib = blockIdx.x * 128, head = blockIdx.y, b = blockIdx.z;
    int bh = b * HEADS + head;

    int tid = threadIdx.x, wid = tid >> 5, lid = tid & 31;
    int g = lid >> 2;
    int c4 = (lid & 3) * 4;

    // ---- persistent Q tile: pure 16B copies from pre-converted gmem ----
    {
        const __nv_bfloat16* qsrc = g_qc + ((size_t)bh * NPIX + ib) * 64;
        #pragma unroll
        for (int c = tid; c < 1024; c += 256) {
            int row = c >> 3, seg = c & 7;
            *(float4*)(sb + Q_OFF + row * PQK + seg * 16) =
                *(const float4*)(qsrc + (size_t)c * 8);
        }
    }
    if (tid < 128) { row_m[tid] = -1e30f; row_l[tid] = 0.f; }

    float oa[2][4][4];
    #pragma unroll
    for (int a = 0; a < 2; a++)
        #pragma unroll
        for (int bq = 0; bq < 4; bq++)
            #pragma unroll
            for (int e = 0; e < 4; e++) oa[a][bq][e] = 0.f;

    int swr = (wid >> 2) * 64, swc = (wid & 3) * 32;   // S-phase: 64x32 tile
    int pwr = (wid >> 1) * 32, pwc = (wid & 1) * 32;   // PV-phase: 32x32 tile
    __syncthreads();

    for (int jt = 0; jt < 32; jt++) {
        int jb = jt * 128;

        // ---- K / V tile loads: pure 16B copies ----
        {
            const __nv_bfloat16* ksrc = g_kc + ((size_t)bh * NPIX + jb) * 64;
            #pragma unroll
            for (int c = tid; c < 1024; c += 256) {
                int row = c >> 3, seg = c & 7;
                *(float4*)(sb + K_OFF + row * PQK + seg * 16) =
                    *(const float4*)(ksrc + (size_t)c * 8);
            }
            const __nv_bfloat16* vsrc = g_vc + (size_t)(bh * 32 + jt) * 2 * 8192;
            #pragma unroll
            for (int c = tid; c < 1024; c += 256) {
                int d = c >> 4, seg = c & 15;
                *(float4*)(sb + VH_OFF + d * PVROW + seg * 16) =
                    *(const float4*)(vsrc + (size_t)c * 8);
                *(float4*)(sb + VL_OFF + d * PVROW + seg * 16) =
                    *(const float4*)(vsrc + 8192 + (size_t)c * 8);
            }
        }
        __syncthreads();

        // ---- S = Q K^T  (3-term split, 2 k-steps of 16) ----
        float sa[4][4][4];
        #pragma unroll
        for (int mi = 0; mi < 4; mi++)
            #pragma unroll
            for (int ni = 0; ni < 4; ni++)
                #pragma unroll
                for (int e = 0; e < 4; e++) sa[mi][ni][e] = 0.f;

        #pragma unroll 1
        for (int term = 0; term < 3; term++) {
            int aL = (term == 2) ? 64 : 0;
            int bL = (term == 1) ? 64 : 0;
            const char* aBase = sb + Q_OFF + (swr + g) * PQK + aL + c4;
            const char* bBase = sb + K_OFF + (swc + g) * PQK + bL + c4;
            #pragma unroll
            for (int ks = 0; ks < 2; ks++) {
                int kB = ks * 32;
                uint32_t afr[4][4], bfr[4][2];
                #pragma unroll
                for (int mi = 0; mi < 4; mi++) {
                    const char* ap = aBase + mi * 16 * PQK + kB;
                    afr[mi][0] = *(const uint32_t*)ap;
                    afr[mi][1] = *(const uint32_t*)(ap + 8 * PQK);
                    afr[mi][2] = *(const uint32_t*)(ap + 16);
                    afr[mi][3] = *(const uint32_t*)(ap + 8 * PQK + 16);
                }
                #pragma unroll
                for (int ni = 0; ni < 4; ni++) {
                    const char* bp = bBase + ni * 8 * PQK + kB;
                    bfr[ni][0] = *(const uint32_t*)bp;
                    bfr[ni][1] = *(const uint32_t*)(bp + 16);
                }
                #pragma unroll
                for (int mi = 0; mi < 4; mi++)
                    #pragma unroll
                    for (int ni = 0; ni < 4; ni++)
                        mma16816(sa[mi][ni], afr[mi], bfr[ni]);
            }
        }
        #pragma unroll
        for (int mi = 0; mi < 4; mi++)
            #pragma unroll
            for (int ni = 0; ni < 4; ni++) {
                int r = swr + mi * 16 + g;
                int colB = (swc + ni * 8) * 4 + c4 * 2;
                *(float2*)(sb + S_OFF + r * PSROW + colB) = make_float2(sa[mi][ni][0], sa[mi][ni][1]);
                *(float2*)(sb + S_OFF + (r + 8) * PSROW + colB) = make_float2(sa[mi][ni][2], sa[mi][ni][3]);
            }
        __syncthreads();

        // ---- online softmax: 2 threads per row; row half buffered in regs ----
        {
            int r = tid >> 1, p = tid & 1;
            const char* rowp = sb + S_OFF + r * PSROW + p * 256;
            float4 vbuf[16];
            #pragma unroll
            for (int q = 0; q < 16; q++) vbuf[q] = *(const float4*)(rowp + q * 16);
            float mx = -1e30f;
            #pragma unroll
            for (int q = 0; q < 16; q++) {
                float4 v = vbuf[q];
                mx = fmaxf(mx, fmaxf(fmaxf(v.x, v.y), fmaxf(v.z, v.w)));
            }
            mx = fmaxf(mx, __shfl_xor_sync(0xffffffffu, mx, 1));
            float m_old = row_m[r];
            float m_new = fmaxf(m_old, mx);
            float ls = 0.f;
            char* hip = sb + S_OFF + r * PSROW + p * 128;
            char* lop = sb + S_OFF + r * PSROW + 280 + p * 128;
            #pragma unroll 4
            for (int q = 0; q < 16; q++) {
                float4 v = vbuf[q];
                float p0 = __expf((v.x - m_new) * scale);
                float p1 = __expf((v.y - m_new) * scale);
                float p2 = __expf((v.z - m_new) * scale);
                float p3 = __expf((v.w - m_new) * scale);
                ls += (p0 + p1) + (p2 + p3);
                __nv_bfloat16 h0 = __float2bfloat16(p0), h1 = __float2bfloat16(p1);
                __nv_bfloat16 h2 = __float2bfloat16(p2), h3 = __float2bfloat16(p3);
                __nv_bfloat162 hw0; hw0.x = h0; hw0.y = h1;
                __nv_bfloat162 hw1; hw1.x = h2; hw1.y = h3;
                *(uint32_t*)(hip + q * 8)     = *(uint32_t*)&hw0;
                *(uint32_t*)(hip + q * 8 + 4) = *(uint32_t*)&hw1;
                __nv_bfloat162 lw0, lw1;
                lw0.x = __float2bfloat16(p0 - __bfloat162float(h0));
                lw0.y = __float2bfloat16(p1 - __bfloat162float(h1));
                lw1.x = __float2bfloat16(p2 - __bfloat162float(h2));
                lw1.y = __float2bfloat16(p3 - __bfloat162float(h3));
                *(uint32_t*)(lop + q * 8)     = *(uint32_t*)&lw0;
                *(uint32_t*)(lop + q * 8 + 4) = *(uint32_t*)&lw1;
            }
            ls += __shfl_xor_sync(0xffffffffu, ls, 1);
            if (p == 0) {
                float cf = __expf((m_old - m_new) * scale);
                corr[r] = cf;
                row_l[r] = row_l[r] * cf + ls;
                row_m[r] = m_new;
            }
        }
        __syncthreads();

        // ---- O = O*corr + P V^T (3-term split, 8 k-steps of 16) ----
        #pragma unroll
        for (int mi = 0; mi < 2; mi++) {
            float c0 = corr[pwr + mi * 16 + g];
            float c1 = corr[pwr + mi * 16 + g + 8];
            #pragma unroll
            for (int ni = 0; ni < 4; ni++) {
                oa[mi][ni][0] *= c0; oa[mi][ni][1] *= c0;
                oa[mi][ni][2] *= c1; oa[mi][ni][3] *= c1;
            }
        }
        #pragma unroll 1
        for (int term = 0; term < 3; term++) {
            int aL = (term == 2) ? 280 : 0;
            const char* vBase = sb + ((term == 1) ? VL_OFF : VH_OFF) + (pwc + g) * PVROW + c4;
            const char* pBase = sb + S_OFF + (pwr + g) * PSROW + aL + c4;
            #pragma unroll 2
            for (int ks = 0; ks < 8; ks++) {
                int kB = ks * 32;
                uint32_t afr[2][4], bfr[4][2];
                #pragma unroll
                for (int mi = 0; mi < 2; mi++) {
                    const char* ap = pBase + mi * 16 * PSROW + kB;
                    afr[mi][0] = *(const uint32_t*)ap;
                    afr[mi][1] = *(const uint32_t*)(ap + 8 * PSROW);
                    afr[mi][2] = *(const uint32_t*)(ap + 16);
                    afr[mi][3] = *(const uint32_t*)(ap + 8 * PSROW + 16);
                }
                #pragma unroll
                for (int ni = 0; ni < 4; ni++) {
                    const char* bp = vBase + ni * 8 * PVROW + kB;
                    bfr[ni][0] = *(const uint32_t*)bp;
                    bfr[ni][1] = *(const uint32_t*)(bp + 16);
                }
                #pragma unroll
                for (int mi = 0; mi < 2; mi++)
                    #pragma unroll
                    for (int ni = 0; ni < 4; ni++)
                        mma16816(oa[mi][ni], afr[mi], bfr[ni]);
            }
        }
        __syncthreads();
    }

    // ---- epilogue: normalize, transpose via smem stage, store -------------
    float* stage = (float*)sb;   // 64 x 132 floats, overlays Q/K (dead now)
    #pragma unroll
    for (int mi = 0; mi < 2; mi++) {
        int r0 = pwr + mi * 16 + g;
        float i0 = 1.f / row_l[r0];
        float i1 = 1.f / row_l[r0 + 8];
        #pragma unroll
        for (int ni = 0; ni < 4; ni++) {
            int d0 = pwc + ni * 8 + (c4 >> 1);
            stage[d0 * 132 + r0]       = oa[mi][ni][0] * i0;
            stage[(d0 + 1) * 132 + r0] = oa[mi][ni][1] * i0;
            stage[d0 * 132 + r0 + 8]       = oa[mi][ni][2] * i1;
            stage[(d0 + 1) * 132 + r0 + 8] = oa[mi][ni][3] * i1;
        }
    }
    __syncthreads();
    {
        float* yout = g_y + ((size_t)b * DIMC + head * 64) * NPIX + ib;
        for (int f = tid; f < 8192; f += 256) {
            int d = f >> 7, i = f & 127;
            yout[(size_t)d * NPIX + i] = stage[d * 132 + i];
        }
    }
}

// ---------------- depthwise 3x3 pe conv + residual add ---------------------
__global__ __launch_bounds__(256) void pe_add_kernel()
{
    int idx = blockIdx.x * 256 + threadIdx.x;
    if (idx >= NB * DIMC * NPIX) return;
    int n = idx & 4095;
    int c = (idx >> 12) & 255;
    int b = idx >> 20;
    int hh = n >> 6, ww = n & 63;
    int head = c >> 6, dv = c & 63;
    const float* V = g_qkv + ((size_t)(b * HEADS + head) * 128 + 64 + dv) * NPIX;
    const float* w = g_wpe + c * 9;
    float s = g_bpe[c];
    #pragma unroll
    for (int ky = -1; ky <= 1; ky++) {
        int yy = hh + ky;
        if (yy < 0 || yy > 63) continue;
        #pragma unroll
        for (int kx = -1; kx <= 1; kx++) {
            int xx = ww + kx;
            if (xx < 0 || xx > 63) continue;
            s = fmaf(w[(ky + 1) * 3 + kx + 1], V[yy * 64 + xx], s);
        }
    }
    g_y[idx] += s;
}

// ---------------- launch ----------------------------------------------------
extern "C" void kernel_launch(void* const* d_in, const int* in_sizes, int n_in,
                              void* d_out, int out_size)
{
    const float* x = (const float*)d_in[0];

    cudaFuncSetAttribute(attn_mma_kernel, cudaFuncAttributeMaxDynamicSharedMemorySize,
                         ATTN_SMEM);

    fold_kernel<<<64, 256>>>(
        (const float*)d_in[1], (const float*)d_in[2], (const float*)d_in[3],
        (const float*)d_in[4], (const float*)d_in[5],
        (const float*)d_in[6], (const float*)d_in[7], (const float*)d_in[8],
        (const float*)d_in[9], (const float*)d_in[10],
        (const float*)d_in[11], (const float*)d_in[12], (const float*)d_in[13],
        (const float*)d_in[14], (const float*)d_in[15]);

    dim3 gq(NPIX / 128, HIDDEN / 128, NB);
    gemm_qkv_kernel<<<gq, 256>>>(x);

    dim3 gc(32, NB * HEADS);
    qkv_convert_kernel<<<gc, 256>>>();

    dim3 ga(NPIX / 128, HEADS, NB);
    attn_mma_kernel<<<ga, 256, ATTN_SMEM>>>();

    pe_add_kernel<<<(NB * DIMC * NPIX) / 256, 256>>>();

    dim3 gp(NPIX / 128, DIMC / 128, NB);
    gemm_proj_kernel<<<gp, 256>>>((float*)d_out);
}